// round 10
// baseline (speedup 1.0000x reference)
#include <cuda_runtime.h>
#include <math.h>

typedef unsigned long long u64;

#define N_ENT 4096
#define BATCH 4
#define NHID  3
#define ROWS_T (BATCH*N_ENT)     // 16384
#define RBLK_MAX 112             // rows per CTA (pad to 2)
#define NSTAGE 4
#define TILE_BYTES 32768         // 2 rows x 4096 ints x 4B
#define NTHR 512

// dynamic smem layout for k_main:
//   [0, 131072)      sAdj: 4 stages x 32KB
//   [131072, +896)   sRow: RBLK_MAX float2 (rv, w0')
//   [131968, +28672) sPart: 16 warps x RBLK_MAX x 4 floats
//   [160640, +128)   mbarriers: full[4] @ +0, empty[4] @ +64 (16B apart)
#define SROW_OFF   131072
#define SPART_OFF  (SROW_OFF + RBLK_MAX*8)
#define SMBAR_OFF  (SPART_OFF + 16*RBLK_MAX*4*4)
#define SMEM_MAIN  (SMBAR_OFF + 128)     // 160768 B

// ---------------- device scratch ----------------
__device__ float4  g_tabH[N_ENT];        // h0, h1, h2, dst
__device__ float   g_src[N_ENT];
__device__ unsigned g_dmax_u = 0;        // encoded float max (idempotent)
__device__ float   g_x[ROWS_T*NHID];

__device__ __forceinline__ unsigned fenc(float f) {
    unsigned u = __float_as_uint(f);
    return (u & 0x80000000u) ? ~u : (u | 0x80000000u);
}
__device__ __forceinline__ float fdec(unsigned e) {
    return (e & 0x80000000u) ? __uint_as_float(e & 0x7fffffffu)
                             : __uint_as_float(~e);
}
__device__ __forceinline__ void mbar_init(unsigned m, unsigned cnt) {
    asm volatile("mbarrier.init.shared.b64 [%0], %1;" :: "r"(m), "r"(cnt) : "memory");
}
__device__ __forceinline__ void mbar_expect_tx(unsigned m, unsigned bytes) {
    asm volatile("mbarrier.arrive.expect_tx.shared.b64 _, [%0], %1;"
                 :: "r"(m), "r"(bytes) : "memory");
}
__device__ __forceinline__ void mbar_arrive(unsigned m) {
    asm volatile("mbarrier.arrive.shared.b64 _, [%0];" :: "r"(m) : "memory");
}
__device__ __forceinline__ void mbar_wait(unsigned m, unsigned phase) {
    asm volatile(
        "{\n\t.reg .pred P;\n"
        "W_%=:\n\t"
        "mbarrier.try_wait.parity.acquire.cta.shared::cta.b64 P, [%0], %1, 0x989680;\n\t"
        "@!P bra W_%=;\n\t}"
        :: "r"(m), "r"(phase) : "memory");
}
__device__ __forceinline__ void bulk_cp(unsigned dst, const void* src,
                                        unsigned bytes, unsigned m) {
    asm volatile(
        "cp.async.bulk.shared::cta.global.mbarrier::complete_tx::bytes "
        "[%0], [%1], %2, [%3];"
        :: "r"(dst), "l"(src), "r"(bytes), "r"(m) : "memory");
}

// ---------------- K1: h = emb@W — coalesced via smem staging ----------------
// 32 blocks x 128 threads; block stages 128 node embeddings (32KB) into smem
// with fully coalesced float4 loads (16 iterations x 128 threads = 2048
// float4 = 128 rows), then each thread computes one node.
__global__ void k_node(const float* __restrict__ emb,
                       const float* __restrict__ W,
                       const float* __restrict__ a) {
    __shared__ float sE[128*65];   // padded rows -> conflict-free LDS
    __shared__ float sW[192];
    __shared__ float sa[6];
    __shared__ float sm[128];
    int t = threadIdx.x;
    if (t < 96) { sW[t] = W[t]; sW[t+96] = W[t+96]; }
    if (t < 6) sa[t] = a[t];

    // coalesced load of 128 rows x 64 floats = 2048 float4
    const float4* e4 = (const float4*)emb + (size_t)blockIdx.x * 2048;
#pragma unroll
    for (int i = 0; i < 16; i++) {
        int idx = i * 128 + t;
        float4 vv = __ldg(e4 + idx);
        float* d = &sE[(idx >> 4) * 65 + (idx & 15) * 4];
        d[0] = vv.x; d[1] = vv.y; d[2] = vv.z; d[3] = vv.w;
    }
    __syncthreads();

    const float* er = &sE[t * 65];
    float h0 = 0.f, h1 = 0.f, h2 = 0.f;
#pragma unroll
    for (int k = 0; k < 64; k++) {
        float e = er[k];
        h0 += e * sW[k*3+0];
        h1 += e * sW[k*3+1];
        h2 += e * sW[k*3+2];
    }
    float src = h0*sa[0] + h1*sa[1] + h2*sa[2];
    float dst = h0*sa[3] + h1*sa[4] + h2*sa[5];
    int i = blockIdx.x * 128 + t;
    g_tabH[i] = make_float4(h0, h1, h2, dst);
    g_src[i]  = src;

    sm[t] = dst;
    __syncthreads();
    for (int s = 64; s > 0; s >>= 1) {
        if (t < s) sm[t] = fmaxf(sm[t], sm[t+s]);
        __syncthreads();
    }
    if (t == 0) atomicMax(&g_dmax_u, fenc(sm[0]));
}

// ---------------- K2: main pass — ring + f32x2 packed accumulation --------
// Row-normalized weights (divide row by u = exp(z-m)): edge weight =
// fmax(p_k, rv*q_k) with rv = exp(-0.8z); non-edge = exp(9e-15 - z).
// The scale cancels in num/den. Two tile rows packed into f32x2 lanes.
__global__ void __launch_bounds__(NTHR, 1) k_main(const int* __restrict__ adj) {
    extern __shared__ char dsm[];
    float2* sRow  = (float2*)(dsm + SROW_OFF);
    float*  sPart = (float*)(dsm + SPART_OFF);
    unsigned sb   = (unsigned)__cvta_generic_to_shared(dsm);
    unsigned mb_full  = sb + SMBAR_OFF;        // full[s]  @ +16*s
    unsigned mb_empty = sb + SMBAR_OFF + 64;   // empty[s] @ +16*s

    int t = threadIdx.x, w = t >> 5, lane = t & 31;
    int j0 = w * 256 + lane * 8;

    float dm = fdec(g_dmax_u);

    // per-lane column tables: p,q scalar; h packed (x,x) for f32x2 FMA
    float p[8], q[8];
    u64 H0[8], H1[8], H2[8];
#pragma unroll
    for (int k = 0; k < 8; k++) {
        float4 H = g_tabH[j0 + k];
        float d = H.w - dm;
        p[k] = expf(d);
        q[k] = expf(0.2f * d);
        asm("mov.b64 %0, {%1, %1};" : "=l"(H0[k]) : "f"(H.x));
        asm("mov.b64 %0, {%1, %1};" : "=l"(H1[k]) : "f"(H.y));
        asm("mov.b64 %0, {%1, %1};" : "=l"(H2[k]) : "f"(H.z));
    }

    int G = gridDim.x;
    int rblk = (((ROWS_T + G - 1) / G) + 1) & ~1;    // mult of 2
    if (rblk > RBLK_MAX) rblk = RBLK_MAX;
    int r_begin = blockIdx.x * rblk;
    int iters = rblk >> 1;                            // 2 rows per tile

    // per-row constants: rv = exp(-0.8z), w0' = exp(9e-15 - z)
    for (int r = t; r < rblk; r += NTHR) {
        int row = min(r_begin + r, ROWS_T - 1);
        float src = g_src[row & (N_ENT - 1)];
        float z  = src + dm;
        sRow[r] = make_float2(expf(-0.8f * z), expf(9e-15f - z));
    }

    if (t == 0) {
#pragma unroll
        for (int s = 0; s < NSTAGE; s++) {
            mbar_init(mb_full  + 16*s, 1);
            mbar_init(mb_empty + 16*s, NTHR);
        }
    }
    __syncthreads();
    asm volatile("fence.proxy.async.shared::cta;" ::: "memory");

    auto issue = [&](int j) {
        int s = j & (NSTAGE - 1);
        unsigned m = mb_full + 16*s;
        mbar_expect_tx(m, TILE_BYTES);
        int rr = min(r_begin + j*2, ROWS_T - 2);
        bulk_cp(sb + (unsigned)(s * TILE_BYTES),
                adj + ((size_t)rr << 12), TILE_BYTES, m);
    };

    if (t == 0)
        for (int j = 0; j < NSTAGE && j < iters; j++) issue(j);

    int myoff = w * 1024 + lane * 32;     // byte offset of lane's 8 cols in a row

    for (int it = 0; it < iters; it++) {
        int s = it & (NSTAGE - 1);
        mbar_wait(mb_full + 16*s, (it >> 2) & 1);

        const char* sT = dsm + s * TILE_BYTES;
        float2 rcA = sRow[it*2 + 0];
        float2 rcB = sRow[it*2 + 1];

        int4 A0 = *(const int4*)(sT + myoff);
        int4 B0 = *(const int4*)(sT + myoff + 16);
        int4 A1 = *(const int4*)(sT + 16384 + myoff);
        int4 B1 = *(const int4*)(sT + 16384 + myoff + 16);
        int va0[8], va1[8];
        *(int4*)&va0[0] = A0; *(int4*)&va0[4] = B0;
        *(int4*)&va1[0] = A1; *(int4*)&va1[4] = B1;

        u64 acc0 = 0, acc1 = 0, acc2 = 0, acc3 = 0;
#pragma unroll
        for (int k = 0; k < 8; k++) {
            float t0 = fmaxf(p[k], rcA.x * q[k]);
            float t1 = fmaxf(p[k], rcB.x * q[k]);
            float c0 = (va0[k] > 0) ? t0 : rcA.y;
            float c1 = (va1[k] > 0) ? t1 : rcB.y;
            u64 c2;
            asm("mov.b64 %0, {%1, %2};" : "=l"(c2) : "f"(c0), "f"(c1));
            asm("add.rn.f32x2 %0, %0, %1;" : "+l"(acc0) : "l"(c2));
            asm("fma.rn.f32x2 %0, %1, %2, %0;" : "+l"(acc1) : "l"(c2), "l"(H0[k]));
            asm("fma.rn.f32x2 %0, %1, %2, %0;" : "+l"(acc2) : "l"(c2), "l"(H1[k]));
            asm("fma.rn.f32x2 %0, %1, %2, %0;" : "+l"(acc3) : "l"(c2), "l"(H2[k]));
        }

        // done reading stage s
        mbar_arrive(mb_empty + 16*s);

        float v[8];
        asm("mov.b64 {%0, %1}, %2;" : "=f"(v[0]), "=f"(v[4]) : "l"(acc0));
        asm("mov.b64 {%0, %1}, %2;" : "=f"(v[1]), "=f"(v[5]) : "l"(acc1));
        asm("mov.b64 {%0, %1}, %2;" : "=f"(v[2]), "=f"(v[6]) : "l"(acc2));
        asm("mov.b64 {%0, %1}, %2;" : "=f"(v[3]), "=f"(v[7]) : "l"(acc3));

        // butterfly transpose-reduce (8 values): lane i<8 -> warp total of v[i]
#pragma unroll
        for (int d = 4; d >= 1; d >>= 1) {
            int bit = (lane & d) ? 1 : 0;
#pragma unroll
            for (int k = 0; k < d; k++) {
                float snd = bit ? v[k] : v[k+d];
                float tmp = __shfl_xor_sync(0xffffffffu, snd, d);
                v[k] = (bit ? v[k+d] : v[k]) + tmp;
            }
        }
        v[0] += __shfl_xor_sync(0xffffffffu, v[0], 8);
        v[0] += __shfl_xor_sync(0xffffffffu, v[0], 16);

        if (lane < 8)
            sPart[w * (RBLK_MAX*4) + it*8 + lane] = v[0];

        // producer refills this stage 4 tiles ahead
        if (t == 0) {
            int j = it + NSTAGE;
            if (j < iters) {
                mbar_wait(mb_empty + 16*s, (it >> 2) & 1);
                issue(j);
            }
        }
    }

    __syncthreads();

    // epilogue: combine 16 warp slabs -> x = ELU(num/den)
    for (int r = t; r < rblk; r += NTHR) {
        int row = r_begin + r;
        if (row >= ROWS_T) break;
        float den = 0.f, n0 = 0.f, n1 = 0.f, n2 = 0.f;
#pragma unroll
        for (int ww = 0; ww < 16; ww++) {
            const float* sp = &sPart[ww * (RBLK_MAX*4) + r*4];
            den += sp[0]; n0 += sp[1]; n1 += sp[2]; n2 += sp[3];
        }
        float inv = 1.0f / den;
        float x0 = n0 * inv, x1 = n1 * inv, x2 = n2 * inv;
        x0 = (x0 > 0.f) ? x0 : (expf(x0) - 1.f);
        x1 = (x1 > 0.f) ? x1 : (expf(x1) - 1.f);
        x2 = (x2 > 0.f) ? x2 : (expf(x2) - 1.f);
        float* xp = g_x + (size_t)row * NHID;
        xp[0] = x0; xp[1] = x1; xp[2] = x2;
    }
}

// ---------------- K3: out = x @ fc1_w.T + b (w read once per o) ----------
__global__ void k_fc(const float* __restrict__ w,
                     const float* __restrict__ bias,
                     float* __restrict__ out) {
    int o = blockIdx.x;          // 0..99
    int t = threadIdx.x;         // 512
    int wp = t >> 5, lane = t & 31;
    const int K4 = (N_ENT*NHID)/4;            // 3072 float4 per batch
    const float4* wr = (const float4*)(w + (size_t)o * (N_ENT*NHID));
    const float4* xv = (const float4*)g_x;

    float a0 = 0.f, a1 = 0.f, a2 = 0.f, a3 = 0.f;
#pragma unroll
    for (int i = 0; i < 6; i++) {
        int k = i * 512 + t;
        float4 wv = __ldg(wr + k);
        float4 xa = xv[k];
        float4 xb = xv[K4 + k];
        float4 xc = xv[2*K4 + k];
        float4 xd = xv[3*K4 + k];
        a0 += wv.x*xa.x + wv.y*xa.y + wv.z*xa.z + wv.w*xa.w;
        a1 += wv.x*xb.x + wv.y*xb.y + wv.z*xb.z + wv.w*xb.w;
        a2 += wv.x*xc.x + wv.y*xc.y + wv.z*xc.z + wv.w*xc.w;
        a3 += wv.x*xd.x + wv.y*xd.y + wv.z*xd.z + wv.w*xd.w;
    }
#pragma unroll
    for (int off = 16; off; off >>= 1) {
        a0 += __shfl_xor_sync(0xffffffffu, a0, off);
        a1 += __shfl_xor_sync(0xffffffffu, a1, off);
        a2 += __shfl_xor_sync(0xffffffffu, a2, off);
        a3 += __shfl_xor_sync(0xffffffffu, a3, off);
    }
    __shared__ float s4[4][16];
    if (lane == 0) {
        s4[0][wp] = a0; s4[1][wp] = a1; s4[2][wp] = a2; s4[3][wp] = a3;
    }
    __syncthreads();
    if (t < 4) {
        float s = 0.f;
#pragma unroll
        for (int i = 0; i < 16; i++) s += s4[t][i];
        out[t*100 + o] = s + bias[o];
    }
}

// ---------------- launcher ----------------
extern "C" void kernel_launch(void* const* d_in, const int* in_sizes, int n_in,
                              void* d_out, int out_size) {
    const int*   adj  = (const int*)  d_in[0];
    const float* emb  = (const float*)d_in[1];
    const float* W    = (const float*)d_in[2];
    const float* a    = (const float*)d_in[3];
    const float* fc1w = (const float*)d_in[4];
    const float* fc1b = (const float*)d_in[5];
    float* out = (float*)d_out;

    static_assert(SMEM_MAIN <= 227*1024, "smem budget");
    cudaFuncSetAttribute(k_main, cudaFuncAttributeMaxDynamicSharedMemorySize,
                         SMEM_MAIN);

    k_node<<<32, 128>>>(emb, W, a);

    int sms = 148;
    int dev = 0;
    if (cudaGetDevice(&dev) == cudaSuccess) {
        int v = 0;
        if (cudaDeviceGetAttribute(&v, cudaDevAttrMultiProcessorCount, dev) == cudaSuccess && v > 0)
            sms = v;
    }
    k_main<<<sms, NTHR, SMEM_MAIN>>>(adj);

    k_fc<<<100, 512>>>(fc1w, fc1b, out);
}